// round 1
// baseline (speedup 1.0000x reference)
#include <cuda_runtime.h>
#include <math.h>

#define SEQ   4096
#define MODEL 2048
#define NH    16
#define HD    128
#define QKV_N (3*MODEL)

// Scratch buffers (allocation-free rule: __device__ globals)
__device__ float g_hidden[(size_t)SEQ * QKV_N];   // 4096 x 6144
__device__ float g_z[(size_t)SEQ * MODEL];        // 4096 x 2048

// ---------------------------------------------------------------------------
// SGEMM: C[M,N] = A[M,K] @ B[K,N] + bias[N]   (all row-major, fp32)
// 128x128 tile, BK=32, 256 threads, 8x8 microtile per thread.
// ---------------------------------------------------------------------------
__global__ __launch_bounds__(256) void sgemm_bias(
    const float* __restrict__ A, const float* __restrict__ B,
    const float* __restrict__ bias, float* __restrict__ C,
    int M, int N, int K)
{
    __shared__ float As[32 * 132];   // As[k][row], k-stride 132 (pad for store conflicts)
    __shared__ float Bs[32 * 128];   // Bs[k][col]

    const int tid  = threadIdx.x;
    const int row0 = blockIdx.y * 128;
    const int col0 = blockIdx.x * 128;
    const int tx   = tid & 15;
    const int ty   = tid >> 4;

    // global load mappings (fully coalesced)
    const int ar = tid >> 3;          // 0..31 (row within 128, +32*i)
    const int ac = (tid & 7) * 4;     // 0..28 (k offset)
    const int br = tid >> 5;          // 0..7  (k row, +8*i)
    const int bc = (tid & 31) * 4;    // 0..124 (col)

    float acc[8][8];
    #pragma unroll
    for (int i = 0; i < 8; i++)
        #pragma unroll
        for (int j = 0; j < 8; j++) acc[i][j] = 0.f;

    for (int k0 = 0; k0 < K; k0 += 32) {
        __syncthreads();
        #pragma unroll
        for (int i = 0; i < 4; i++) {
            float4 a4 = *(const float4*)(A + (size_t)(row0 + ar + 32*i) * K + k0 + ac);
            int rowi = ar + 32*i;
            As[(ac+0)*132 + rowi] = a4.x;
            As[(ac+1)*132 + rowi] = a4.y;
            As[(ac+2)*132 + rowi] = a4.z;
            As[(ac+3)*132 + rowi] = a4.w;
        }
        #pragma unroll
        for (int i = 0; i < 4; i++) {
            float4 b4 = *(const float4*)(B + (size_t)(k0 + br + 8*i) * N + col0 + bc);
            *(float4*)&Bs[(br + 8*i)*128 + bc] = b4;
        }
        __syncthreads();

        #pragma unroll
        for (int k = 0; k < 32; k++) {
            float4 a0 = *(const float4*)&As[k*132 + ty*4];
            float4 a1 = *(const float4*)&As[k*132 + 64 + ty*4];
            float4 b0 = *(const float4*)&Bs[k*128 + tx*4];
            float4 b1 = *(const float4*)&Bs[k*128 + 64 + tx*4];
            float av[8] = {a0.x,a0.y,a0.z,a0.w,a1.x,a1.y,a1.z,a1.w};
            float bv[8] = {b0.x,b0.y,b0.z,b0.w,b1.x,b1.y,b1.z,b1.w};
            #pragma unroll
            for (int i = 0; i < 8; i++)
                #pragma unroll
                for (int j = 0; j < 8; j++)
                    acc[i][j] += av[i] * bv[j];
        }
    }

    float4 bias0 = *(const float4*)(bias + col0 + tx*4);
    float4 bias1 = *(const float4*)(bias + col0 + 64 + tx*4);
    #pragma unroll
    for (int i = 0; i < 8; i++) {
        int r = row0 + ty*4 + (i & 3) + (i >> 2) * 64;
        float4 v0 = make_float4(acc[i][0] + bias0.x, acc[i][1] + bias0.y,
                                acc[i][2] + bias0.z, acc[i][3] + bias0.w);
        float4 v1 = make_float4(acc[i][4] + bias1.x, acc[i][5] + bias1.y,
                                acc[i][6] + bias1.z, acc[i][7] + bias1.w);
        *(float4*)(C + (size_t)r * N + col0 + tx*4)      = v0;
        *(float4*)(C + (size_t)r * N + col0 + 64 + tx*4) = v1;
    }
}

// ---------------------------------------------------------------------------
// Flash attention (fp32, causal). Grid: (SEQ/64, NH). 256 threads = 8 warps.
// Warp w owns q-rows [w*8, w*8+8). Score cols: lane, lane+32.
// O accumulator cols: lane*4 .. lane*4+3 (contiguous -> float4 V loads/stores).
// ---------------------------------------------------------------------------
#define FL_SMEM_FLOATS (64*132 + 128*65 + 64*128 + 64*64)
#define FL_SMEM_BYTES  (FL_SMEM_FLOATS * 4)

__global__ __launch_bounds__(256, 1) void flash_attn(
    const float* __restrict__ hidden, float* __restrict__ z)
{
    extern __shared__ float sm[];
    float* Qs = sm;                    // [64][132] (pad for float4 alignment)
    float* KT = sm + 64*132;           // [128][65] K transposed (d-major)
    float* Vs = KT + 128*65;           // [64][128]
    float* Ps = Vs + 64*128;           // [64][64]

    const int h    = blockIdx.y;
    const int qb   = (gridDim.x - 1) - blockIdx.x;  // heavy q-blocks first
    const int tid  = threadIdx.x;
    const int w    = tid >> 5;
    const int lane = tid & 31;
    const int r0   = w * 8;
    const float scale = 0.08838834764831845f;  // 1/sqrt(128)

    const float* Qg = hidden + (size_t)(qb*64) * QKV_N + h*HD;
    const float* Kg = hidden + MODEL   + h*HD;
    const float* Vg = hidden + 2*MODEL + h*HD;

    // Load + scale Q tile [64][128]
    for (int i = tid; i < 64*32; i += 256) {
        int r = i >> 5, d4 = (i & 31) << 2;
        float4 q = *(const float4*)(Qg + (size_t)r * QKV_N + d4);
        q.x *= scale; q.y *= scale; q.z *= scale; q.w *= scale;
        *(float4*)&Qs[r*132 + d4] = q;
    }

    float m_[8], l_[8], o[8][4];
    #pragma unroll
    for (int r = 0; r < 8; r++) {
        m_[r] = -1e30f; l_[r] = 0.f;
        o[r][0] = o[r][1] = o[r][2] = o[r][3] = 0.f;
    }

    const int c0 = lane, c1 = lane + 32;

    for (int kb = 0; kb <= qb; kb++) {
        __syncthreads();
        // Load K (transposed) + V tiles
        for (int i = tid; i < 64*32; i += 256) {
            int c = i >> 5, d4 = (i & 31) << 2;
            size_t roff = (size_t)(kb*64 + c) * QKV_N + d4;
            float4 kv = *(const float4*)(Kg + roff);
            KT[(d4+0)*65 + c] = kv.x;
            KT[(d4+1)*65 + c] = kv.y;
            KT[(d4+2)*65 + c] = kv.z;
            KT[(d4+3)*65 + c] = kv.w;
            float4 vv = *(const float4*)(Vg + roff);
            *(float4*)&Vs[c*128 + d4] = vv;
        }
        __syncthreads();

        // S = Q @ K^T (per warp: 8 rows x 64 cols; per lane 8x2)
        float s0[8], s1[8];
        #pragma unroll
        for (int r = 0; r < 8; r++) { s0[r] = 0.f; s1[r] = 0.f; }

        for (int d = 0; d < 128; d += 4) {
            float k00 = KT[(d+0)*65 + c0];
            float k01 = KT[(d+1)*65 + c0];
            float k02 = KT[(d+2)*65 + c0];
            float k03 = KT[(d+3)*65 + c0];
            float k10 = KT[(d+0)*65 + c1];
            float k11 = KT[(d+1)*65 + c1];
            float k12 = KT[(d+2)*65 + c1];
            float k13 = KT[(d+3)*65 + c1];
            #pragma unroll
            for (int r = 0; r < 8; r++) {
                float4 q = *(const float4*)&Qs[(r0+r)*132 + d];
                s0[r] += q.x*k00; s0[r] += q.y*k01; s0[r] += q.z*k02; s0[r] += q.w*k03;
                s1[r] += q.x*k10; s1[r] += q.y*k11; s1[r] += q.z*k12; s1[r] += q.w*k13;
            }
        }

        // Causal mask on diagonal tile
        if (kb == qb) {
            #pragma unroll
            for (int r = 0; r < 8; r++) {
                int rg = r0 + r;
                if (c0 > rg) s0[r] = -1e30f;
                if (c1 > rg) s1[r] = -1e30f;
            }
        }

        // Online softmax (per-row, warp shuffles)
        #pragma unroll
        for (int r = 0; r < 8; r++) {
            float mx = fmaxf(s0[r], s1[r]);
            #pragma unroll
            for (int off = 16; off > 0; off >>= 1)
                mx = fmaxf(mx, __shfl_xor_sync(0xffffffffu, mx, off));
            float mn    = fmaxf(m_[r], mx);
            float alpha = __expf(m_[r] - mn);
            float p0    = __expf(s0[r] - mn);
            float p1    = __expf(s1[r] - mn);
            float sum   = p0 + p1;
            #pragma unroll
            for (int off = 16; off > 0; off >>= 1)
                sum += __shfl_xor_sync(0xffffffffu, sum, off);
            l_[r] = l_[r]*alpha + sum;
            m_[r] = mn;
            o[r][0] *= alpha; o[r][1] *= alpha; o[r][2] *= alpha; o[r][3] *= alpha;
            Ps[(r0+r)*64 + c0] = p0;
            Ps[(r0+r)*64 + c1] = p1;
        }
        __syncwarp();

        // O += P @ V
        for (int j = 0; j < 64; j += 4) {
            const float* vb = &Vs[j*128 + (lane << 2)];
            float4 v0 = *(const float4*)(vb);
            float4 v1 = *(const float4*)(vb + 128);
            float4 v2 = *(const float4*)(vb + 256);
            float4 v3 = *(const float4*)(vb + 384);
            #pragma unroll
            for (int r = 0; r < 8; r++) {
                float4 p = *(const float4*)&Ps[(r0+r)*64 + j];
                o[r][0] += p.x*v0.x; o[r][0] += p.y*v1.x; o[r][0] += p.z*v2.x; o[r][0] += p.w*v3.x;
                o[r][1] += p.x*v0.y; o[r][1] += p.y*v1.y; o[r][1] += p.z*v2.y; o[r][1] += p.w*v3.y;
                o[r][2] += p.x*v0.z; o[r][2] += p.y*v1.z; o[r][2] += p.z*v2.z; o[r][2] += p.w*v3.z;
                o[r][3] += p.x*v0.w; o[r][3] += p.y*v1.w; o[r][3] += p.z*v2.w; o[r][3] += p.w*v3.w;
            }
        }
        __syncwarp();
    }

    // Normalize and write z[q][h*128 + c]
    #pragma unroll
    for (int r = 0; r < 8; r++) {
        float inv = 1.0f / l_[r];
        float4 ov = make_float4(o[r][0]*inv, o[r][1]*inv, o[r][2]*inv, o[r][3]*inv);
        *(float4*)(z + (size_t)(qb*64 + r0 + r) * MODEL + h*HD + (lane << 2)) = ov;
    }
}

// ---------------------------------------------------------------------------
extern "C" void kernel_launch(void* const* d_in, const int* in_sizes, int n_in,
                              void* d_out, int out_size)
{
    const float* x      = (const float*)d_in[0];
    const float* w_attn = (const float*)d_in[1];
    const float* b_attn = (const float*)d_in[2];
    const float* w_proj = (const float*)d_in[3];
    const float* b_proj = (const float*)d_in[4];
    float* out = (float*)d_out;

    float* hid; float* z;
    cudaGetSymbolAddress((void**)&hid, g_hidden);
    cudaGetSymbolAddress((void**)&z,   g_z);

    cudaFuncSetAttribute(flash_attn,
                         cudaFuncAttributeMaxDynamicSharedMemorySize,
                         FL_SMEM_BYTES);

    // 1) QKV projection: hidden = x @ w_attn + b_attn
    dim3 g1(QKV_N/128, SEQ/128);
    sgemm_bias<<<g1, 256>>>(x, w_attn, b_attn, hid, SEQ, QKV_N, MODEL);

    // 2) causal multi-head attention -> z
    flash_attn<<<dim3(SEQ/64, NH), 256, FL_SMEM_BYTES>>>(hid, z);

    // 3) output projection: out = z @ w_proj + b_proj
    dim3 g2(MODEL/128, SEQ/128);
    sgemm_bias<<<g2, 256>>>(z, w_proj, b_proj, out, SEQ, MODEL, MODEL);
}

// round 4
// speedup vs baseline: 4.7669x; 4.7669x over previous
#include <cuda_runtime.h>
#include <math.h>
#include <stdint.h>

#define SEQ   4096
#define MODEL 2048
#define NH    16
#define HD    128
#define QKV_N (3*MODEL)

// Scratch (__device__ globals: allocation-free rule). Same footprint as the
// known-good R1 binary (134 MB).
__device__ float g_hidden[(size_t)SEQ * QKV_N];
__device__ float g_z[(size_t)SEQ * MODEL];

__device__ __forceinline__ uint32_t f2tf32(float f) {
    uint32_t u; asm("cvt.rna.tf32.f32 %0, %1;" : "=r"(u) : "f"(f)); return u;
}

__device__ __forceinline__ void mma_tf32(float* c, const uint32_t* a,
                                         uint32_t b0, uint32_t b1) {
    asm volatile(
        "mma.sync.aligned.m16n8k8.row.col.f32.tf32.tf32.f32 "
        "{%0,%1,%2,%3}, {%4,%5,%6,%7}, {%8,%9}, {%0,%1,%2,%3};\n"
        : "+f"(c[0]), "+f"(c[1]), "+f"(c[2]), "+f"(c[3])
        : "r"(a[0]), "r"(a[1]), "r"(a[2]), "r"(a[3]), "r"(b0), "r"(b1));
}

__device__ __forceinline__ void cp16(uint32_t dst, const void* src) {
    asm volatile("cp.async.cg.shared.global [%0], [%1], 16;\n" :: "r"(dst), "l"(src));
}
__device__ __forceinline__ void cp_commit() { asm volatile("cp.async.commit_group;\n"); }
template<int N> __device__ __forceinline__ void cp_wait() {
    asm volatile("cp.async.wait_group %0;\n" :: "n"(N));
}

// ---------------------------------------------------------------------------
// tf32 tensor-core GEMM: C[M,N] = A[M,K]@B[K,N] + bias (A,B raw fp32;
// RNA->tf32 conversion happens at fragment load from smem).
// 128x128 tile, BK=16, 256 thr (2x4 warps, 64x32 warp tile), cp.async 4-stage.
// ---------------------------------------------------------------------------
#define GS 4
#define ASTRIDE 20
#define BSTRIDE 136
#define A_TILE (128*ASTRIDE)
#define B_TILE (16*BSTRIDE)
#define GEMM_SMEM ((GS*(A_TILE+B_TILE))*4)

__global__ __launch_bounds__(256, 2) void gemm_tf32(
    const float* __restrict__ A, const float* __restrict__ B,
    const float* __restrict__ bias, float* __restrict__ C,
    int M, int N, int K)
{
    extern __shared__ float gsm[];
    float* As = gsm;                  // [GS][128][ASTRIDE]  (layout [m][k])
    float* Bs = gsm + GS*A_TILE;      // [GS][16][BSTRIDE]   (layout [k][n])

    const int tid  = threadIdx.x;
    const int lane = tid & 31;
    const int warp = tid >> 5;
    const int m0 = (warp >> 2) * 64;
    const int n0 = (warp & 3) * 32;
    const int row0 = blockIdx.y * 128, col0 = blockIdx.x * 128;

    const int art = tid >> 2, acol = (tid & 3) * 4;   // A: 2 rows x 16B
    const int bkr = tid >> 4, bcol = (tid & 15) * 8;  // B: 1 row  x 2x16B

    uint32_t asA = (uint32_t)__cvta_generic_to_shared(As);
    uint32_t asB = (uint32_t)__cvta_generic_to_shared(Bs);
    const int niter = K >> 4;

    auto issue = [&](int t) {
        int st = t & (GS - 1);
        const float* ap = A + (size_t)(row0 + art) * K + t*16 + acol;
        uint32_t ad = asA + (uint32_t)(st*A_TILE + art*ASTRIDE + acol) * 4u;
        cp16(ad, ap);
        cp16(ad + 64u*ASTRIDE*4u, ap + (size_t)64 * K);
        const float* bp = B + (size_t)(t*16 + bkr) * N + col0 + bcol;
        uint32_t bd = asB + (uint32_t)(st*B_TILE + bkr*BSTRIDE + bcol) * 4u;
        cp16(bd, bp);
        cp16(bd + 16u, bp + 4);
    };

    #pragma unroll
    for (int s = 0; s < GS - 1; s++) { issue(s); cp_commit(); }

    float c[4][4][4];
    #pragma unroll
    for (int mi = 0; mi < 4; mi++)
        #pragma unroll
        for (int ni = 0; ni < 4; ni++)
            #pragma unroll
            for (int r = 0; r < 4; r++) c[mi][ni][r] = 0.f;

    for (int i = 0; i < niter; i++) {
        cp_wait<GS-2>();
        __syncthreads();
        if (i + GS - 1 < niter) issue(i + GS - 1);
        cp_commit();

        const float* Ab = As + (size_t)(i & (GS-1)) * A_TILE;
        const float* Bb = Bs + (size_t)(i & (GS-1)) * B_TILE;

        #pragma unroll
        for (int kk = 0; kk < 16; kk += 8) {
            uint32_t af[4][4];
            #pragma unroll
            for (int mi = 0; mi < 4; mi++) {
                const float* p = Ab + (m0 + mi*16 + (lane>>2))*ASTRIDE + kk + (lane&3);
                af[mi][0] = f2tf32(p[0]);
                af[mi][1] = f2tf32(p[8*ASTRIDE]);
                af[mi][2] = f2tf32(p[4]);
                af[mi][3] = f2tf32(p[8*ASTRIDE + 4]);
            }
            #pragma unroll
            for (int ni = 0; ni < 4; ni++) {
                const float* bp = Bb + (kk + (lane&3))*BSTRIDE + n0 + ni*8 + (lane>>2);
                uint32_t b0 = f2tf32(bp[0]);
                uint32_t b1 = f2tf32(bp[4*BSTRIDE]);
                #pragma unroll
                for (int mi = 0; mi < 4; mi++)
                    mma_tf32(c[mi][ni], af[mi], b0, b1);
            }
        }
        __syncthreads();
    }

    #pragma unroll
    for (int ni = 0; ni < 4; ni++) {
        int cc = col0 + n0 + ni*8 + 2*(lane & 3);
        float2 bb = *(const float2*)(bias + cc);
        #pragma unroll
        for (int mi = 0; mi < 4; mi++) {
            int r = row0 + m0 + mi*16 + (lane >> 2);
            float2 v0 = make_float2(c[mi][ni][0] + bb.x, c[mi][ni][1] + bb.y);
            float2 v1 = make_float2(c[mi][ni][2] + bb.x, c[mi][ni][3] + bb.y);
            *(float2*)(C + (size_t)r * N + cc)       = v0;
            *(float2*)(C + (size_t)(r + 8) * N + cc) = v1;
        }
    }
}

// ---------------------------------------------------------------------------
// tf32 tensor-core flash attention (causal). Q block 128, key tile 64.
// 8 warps, each owns 16 q-rows end-to-end. Grid (32, 16) heavy-qb-first.
// ---------------------------------------------------------------------------
#define QS_S 132
#define KS_S 132
#define VS_S 136
#define PS_S 68
#define AT_SMEM ((128*QS_S + 64*KS_S + 64*VS_S + 128*PS_S)*4)

__global__ __launch_bounds__(256, 1) void flash_tf32(
    const float* __restrict__ hidden, float* __restrict__ z)
{
    extern __shared__ uint32_t sm[];
    uint32_t* Qs = sm;                   // [128][QS_S]  Q  (tf32)
    uint32_t* Ks = Qs + 128*QS_S;        // [64][KS_S]   K
    uint32_t* Vs = Ks + 64*KS_S;         // [64][VS_S]   V
    uint32_t* Ps = Vs + 64*VS_S;         // [128][PS_S]  P

    const int h    = blockIdx.y;
    const int qb   = (int)(gridDim.x - 1) - (int)blockIdx.x;
    const int tid  = threadIdx.x;
    const int lane = tid & 31;
    const int warp = tid >> 5;
    const int m0   = warp * 16;
    const int ra   = lane >> 2;
    const int kq   = lane & 3;
    const float scale = 0.08838834764831845f;  // 1/sqrt(128)

    // Load + scale + round Q tile [128][128]
    #pragma unroll
    for (int i = 0; i < 16; i++) {
        int idx = tid + 256*i;
        int r = idx >> 5, d4 = (idx & 31) << 2;
        float4 q = *(const float4*)(hidden + (size_t)(qb*128 + r)*QKV_N + h*HD + d4);
        *(uint4*)&Qs[r*QS_S + d4] = make_uint4(
            f2tf32(q.x*scale), f2tf32(q.y*scale), f2tf32(q.z*scale), f2tf32(q.w*scale));
    }

    float m_a = -1e30f, m_b = -1e30f, l_a = 0.f, l_b = 0.f;
    float o[16][4];
    #pragma unroll
    for (int ni = 0; ni < 16; ni++)
        o[ni][0] = o[ni][1] = o[ni][2] = o[ni][3] = 0.f;

    const int qr_a = qb*128 + m0 + ra;
    const int nkb  = 2*qb + 2;

    for (int kb = 0; kb < nkb; kb++) {
        __syncthreads();
        #pragma unroll
        for (int i = 0; i < 8; i++) {
            int idx = tid + 256*i;
            int r = idx >> 5, d4 = (idx & 31) << 2;
            const float* kp = hidden + (size_t)(kb*64 + r)*QKV_N + MODEL + h*HD + d4;
            float4 kf = *(const float4*)kp;
            *(uint4*)&Ks[r*KS_S + d4] =
                make_uint4(f2tf32(kf.x), f2tf32(kf.y), f2tf32(kf.z), f2tf32(kf.w));
            float4 vf = *(const float4*)(kp + MODEL);
            *(uint4*)&Vs[r*VS_S + d4] =
                make_uint4(f2tf32(vf.x), f2tf32(vf.y), f2tf32(vf.z), f2tf32(vf.w));
        }
        __syncthreads();

        // ---- S = Q @ K^T  (per warp: 16 x 64) ----
        float s[8][4];
        #pragma unroll
        for (int n = 0; n < 8; n++) s[n][0] = s[n][1] = s[n][2] = s[n][3] = 0.f;

        #pragma unroll
        for (int k0 = 0; k0 < 128; k0 += 8) {
            uint32_t a[4];
            const uint32_t* qp = Qs + (m0 + ra)*QS_S + k0 + kq;
            a[0] = qp[0]; a[1] = qp[8*QS_S]; a[2] = qp[4]; a[3] = qp[8*QS_S + 4];
            #pragma unroll
            for (int n = 0; n < 8; n++) {
                const uint32_t* kp2 = Ks + (n*8 + ra)*KS_S + k0 + kq;
                mma_tf32(s[n], a, kp2[0], kp2[4]);
            }
        }

        // ---- causal mask (only near-diagonal tiles) ----
        if (kb >= 2*qb) {
            #pragma unroll
            for (int n = 0; n < 8; n++) {
                int col = kb*64 + n*8 + 2*kq;
                if (col     > qr_a)     s[n][0] = -1e30f;
                if (col + 1 > qr_a)     s[n][1] = -1e30f;
                if (col     > qr_a + 8) s[n][2] = -1e30f;
                if (col + 1 > qr_a + 8) s[n][3] = -1e30f;
            }
        }

        // ---- online softmax (rows ra, ra+8 within warp tile) ----
        float mxa = -1e30f, mxb = -1e30f;
        #pragma unroll
        for (int n = 0; n < 8; n++) {
            mxa = fmaxf(mxa, fmaxf(s[n][0], s[n][1]));
            mxb = fmaxf(mxb, fmaxf(s[n][2], s[n][3]));
        }
        mxa = fmaxf(mxa, __shfl_xor_sync(0xffffffffu, mxa, 1));
        mxa = fmaxf(mxa, __shfl_xor_sync(0xffffffffu, mxa, 2));
        mxb = fmaxf(mxb, __shfl_xor_sync(0xffffffffu, mxb, 1));
        mxb = fmaxf(mxb, __shfl_xor_sync(0xffffffffu, mxb, 2));

        float mna = fmaxf(m_a, mxa), mnb = fmaxf(m_b, mxb);
        float alpha_a = __expf(m_a - mna), alpha_b = __expf(m_b - mnb);
        float suma = 0.f, sumb = 0.f;
        #pragma unroll
        for (int n = 0; n < 8; n++) {
            float p0 = __expf(s[n][0] - mna), p1 = __expf(s[n][1] - mna);
            float p2 = __expf(s[n][2] - mnb), p3 = __expf(s[n][3] - mnb);
            suma += p0 + p1; sumb += p2 + p3;
            uint32_t* pp = Ps + (m0 + ra)*PS_S + n*8 + 2*kq;
            pp[0] = f2tf32(p0); pp[1] = f2tf32(p1);
            pp[8*PS_S] = f2tf32(p2); pp[8*PS_S + 1] = f2tf32(p3);
        }
        suma += __shfl_xor_sync(0xffffffffu, suma, 1);
        suma += __shfl_xor_sync(0xffffffffu, suma, 2);
        sumb += __shfl_xor_sync(0xffffffffu, sumb, 1);
        sumb += __shfl_xor_sync(0xffffffffu, sumb, 2);
        l_a = l_a * alpha_a + suma;
        l_b = l_b * alpha_b + sumb;
        m_a = mna; m_b = mnb;
        #pragma unroll
        for (int ni = 0; ni < 16; ni++) {
            o[ni][0] *= alpha_a; o[ni][1] *= alpha_a;
            o[ni][2] *= alpha_b; o[ni][3] *= alpha_b;
        }
        __syncwarp();

        // ---- O += P @ V  (per warp: 16 x 128) ----
        #pragma unroll
        for (int k0 = 0; k0 < 64; k0 += 8) {
            uint32_t a[4];
            const uint32_t* pp = Ps + (m0 + ra)*PS_S + k0 + kq;
            a[0] = pp[0]; a[1] = pp[8*PS_S]; a[2] = pp[4]; a[3] = pp[8*PS_S + 4];
            #pragma unroll
            for (int ni = 0; ni < 16; ni++) {
                const uint32_t* vp = Vs + (k0 + kq)*VS_S + ni*8 + ra;
                mma_tf32(o[ni], a, vp[0], vp[4*VS_S]);
            }
        }
        __syncwarp();
    }

    // ---- normalize + write z (fp32; proj GEMM converts on load) ----
    float inva = 1.f / l_a, invb = 1.f / l_b;
    #pragma unroll
    for (int ni = 0; ni < 16; ni++) {
        int cc = h*HD + ni*8 + 2*kq;
        int r  = qb*128 + m0 + ra;
        float2 v0 = make_float2(o[ni][0]*inva, o[ni][1]*inva);
        float2 v1 = make_float2(o[ni][2]*invb, o[ni][3]*invb);
        *(float2*)(z + (size_t)r * MODEL + cc)       = v0;
        *(float2*)(z + (size_t)(r + 8) * MODEL + cc) = v1;
    }
}

// ---------------------------------------------------------------------------
extern "C" void kernel_launch(void* const* d_in, const int* in_sizes, int n_in,
                              void* d_out, int out_size)
{
    const float* x      = (const float*)d_in[0];
    const float* w_attn = (const float*)d_in[1];
    const float* b_attn = (const float*)d_in[2];
    const float* w_proj = (const float*)d_in[3];
    const float* b_proj = (const float*)d_in[4];
    float* out = (float*)d_out;

    float *hid, *z;
    cudaGetSymbolAddress((void**)&hid, g_hidden);
    cudaGetSymbolAddress((void**)&z,   g_z);

    cudaFuncSetAttribute(gemm_tf32,  cudaFuncAttributeMaxDynamicSharedMemorySize, GEMM_SMEM);
    cudaFuncSetAttribute(flash_tf32, cudaFuncAttributeMaxDynamicSharedMemorySize, AT_SMEM);

    // 1) QKV projection
    gemm_tf32<<<dim3(QKV_N/128, SEQ/128), 256, GEMM_SMEM>>>(
        x, w_attn, b_attn, hid, SEQ, QKV_N, MODEL);

    // 2) causal multi-head attention
    flash_tf32<<<dim3(SEQ/128, NH), 256, AT_SMEM>>>(hid, z);

    // 3) output projection
    gemm_tf32<<<dim3(MODEL/128, SEQ/128), 256, GEMM_SMEM>>>(
        z, w_proj, b_proj, out, SEQ, MODEL, MODEL);
}

// round 5
// speedup vs baseline: 4.9344x; 1.0351x over previous
#include <cuda_runtime.h>
#include <math.h>
#include <stdint.h>

#define SEQ   4096
#define MODEL 2048
#define NH    16
#define HD    128
#define QKV_N (3*MODEL)

// Scratch (__device__ globals: allocation-free rule)
__device__ float g_hidden[(size_t)SEQ * QKV_N];
__device__ float g_z[(size_t)SEQ * MODEL];
__device__ float g_xr[(size_t)SEQ * MODEL];     // pre-rounded x
__device__ float g_wa[(size_t)MODEL * QKV_N];   // pre-rounded w_attn
__device__ float g_wp[(size_t)MODEL * MODEL];   // pre-rounded w_proj

__device__ __forceinline__ uint32_t f2tf32(float f) {
    uint32_t u; asm("cvt.rna.tf32.f32 %0, %1;" : "=r"(u) : "f"(f)); return u;
}

__device__ __forceinline__ void mma_tf32(float* c, const uint32_t* a,
                                         uint32_t b0, uint32_t b1) {
    asm volatile(
        "mma.sync.aligned.m16n8k8.row.col.f32.tf32.tf32.f32 "
        "{%0,%1,%2,%3}, {%4,%5,%6,%7}, {%8,%9}, {%0,%1,%2,%3};\n"
        : "+f"(c[0]), "+f"(c[1]), "+f"(c[2]), "+f"(c[3])
        : "r"(a[0]), "r"(a[1]), "r"(a[2]), "r"(a[3]), "r"(b0), "r"(b1));
}

__device__ __forceinline__ void cp16(uint32_t dst, const void* src) {
    asm volatile("cp.async.cg.shared.global [%0], [%1], 16;\n" :: "r"(dst), "l"(src));
}
__device__ __forceinline__ void cp_commit() { asm volatile("cp.async.commit_group;\n"); }
template<int N> __device__ __forceinline__ void cp_wait() {
    asm volatile("cp.async.wait_group %0;\n" :: "n"(N));
}

// ---------------------------------------------------------------------------
// Pre-round fp32 -> tf32 (RNA), stored as fp32 bit patterns.
// ---------------------------------------------------------------------------
__global__ void round_tf32_kernel(const float* __restrict__ in,
                                  float* __restrict__ out, int n) {
    int i = (blockIdx.x * blockDim.x + threadIdx.x) * 4;
    int stride = gridDim.x * blockDim.x * 4;
    for (; i < n; i += stride) {
        float4 v = *(const float4*)(in + i);
        *(uint4*)(out + i) = make_uint4(f2tf32(v.x), f2tf32(v.y),
                                        f2tf32(v.z), f2tf32(v.w));
    }
}

// ---------------------------------------------------------------------------
// tf32 tensor-core GEMM: C = A@B + bias. A,B PRE-ROUNDED tf32 bit patterns —
// inner loop is pure LDS+MMA (no cvt). ROUND_OUT: round C to tf32 (for chained
// stages). 128x128 tile, BK=16, 256 thr, cp.async 4-stage.
// ---------------------------------------------------------------------------
#define GS 4
#define ASTRIDE 20
#define BSTRIDE 136
#define A_TILE (128*ASTRIDE)
#define B_TILE (16*BSTRIDE)
#define GEMM_SMEM ((GS*(A_TILE+B_TILE))*4)

template<bool ROUND_OUT>
__global__ __launch_bounds__(256, 2) void gemm_tf32(
    const float* __restrict__ A, const float* __restrict__ B,
    const float* __restrict__ bias, float* __restrict__ C,
    int M, int N, int K)
{
    extern __shared__ uint32_t gsm[];
    uint32_t* As = gsm;                  // [GS][128][ASTRIDE]  ([m][k])
    uint32_t* Bs = gsm + GS*A_TILE;      // [GS][16][BSTRIDE]   ([k][n])

    const int tid  = threadIdx.x;
    const int lane = tid & 31;
    const int warp = tid >> 5;
    const int m0 = (warp >> 2) * 64;
    const int n0 = (warp & 3) * 32;
    const int row0 = blockIdx.y * 128, col0 = blockIdx.x * 128;

    const int art = tid >> 2, acol = (tid & 3) * 4;
    const int bkr = tid >> 4, bcol = (tid & 15) * 8;

    uint32_t asA = (uint32_t)__cvta_generic_to_shared(As);
    uint32_t asB = (uint32_t)__cvta_generic_to_shared(Bs);
    const int niter = K >> 4;

    auto issue = [&](int t) {
        int st = t & (GS - 1);
        const float* ap = A + (size_t)(row0 + art) * K + t*16 + acol;
        uint32_t ad = asA + (uint32_t)(st*A_TILE + art*ASTRIDE + acol) * 4u;
        cp16(ad, ap);
        cp16(ad + 64u*ASTRIDE*4u, ap + (size_t)64 * K);
        const float* bp = B + (size_t)(t*16 + bkr) * N + col0 + bcol;
        uint32_t bd = asB + (uint32_t)(st*B_TILE + bkr*BSTRIDE + bcol) * 4u;
        cp16(bd, bp);
        cp16(bd + 16u, bp + 4);
    };

    #pragma unroll
    for (int s = 0; s < GS - 1; s++) { issue(s); cp_commit(); }

    float c[4][4][4];
    #pragma unroll
    for (int mi = 0; mi < 4; mi++)
        #pragma unroll
        for (int ni = 0; ni < 4; ni++)
            #pragma unroll
            for (int r = 0; r < 4; r++) c[mi][ni][r] = 0.f;

    for (int i = 0; i < niter; i++) {
        cp_wait<GS-2>();
        __syncthreads();   // also protects stage (i-1)%4 == (i+3)%4 for issue below
        if (i + GS - 1 < niter) issue(i + GS - 1);
        cp_commit();

        const uint32_t* Ab = As + (size_t)(i & (GS-1)) * A_TILE;
        const uint32_t* Bb = Bs + (size_t)(i & (GS-1)) * B_TILE;

        #pragma unroll
        for (int kk = 0; kk < 16; kk += 8) {
            uint32_t af[4][4];
            #pragma unroll
            for (int mi = 0; mi < 4; mi++) {
                const uint32_t* p = Ab + (m0 + mi*16 + (lane>>2))*ASTRIDE + kk + (lane&3);
                af[mi][0] = p[0];
                af[mi][1] = p[8*ASTRIDE];
                af[mi][2] = p[4];
                af[mi][3] = p[8*ASTRIDE + 4];
            }
            #pragma unroll
            for (int ni = 0; ni < 4; ni++) {
                const uint32_t* bp = Bb + (kk + (lane&3))*BSTRIDE + n0 + ni*8 + (lane>>2);
                uint32_t b0 = bp[0];
                uint32_t b1 = bp[4*BSTRIDE];
                #pragma unroll
                for (int mi = 0; mi < 4; mi++)
                    mma_tf32(c[mi][ni], af[mi], b0, b1);
            }
        }
        // no trailing barrier: next iteration's top barrier suffices
    }

    #pragma unroll
    for (int ni = 0; ni < 4; ni++) {
        int cc = col0 + n0 + ni*8 + 2*(lane & 3);
        float2 bb = *(const float2*)(bias + cc);
        #pragma unroll
        for (int mi = 0; mi < 4; mi++) {
            int r = row0 + m0 + mi*16 + (lane >> 2);
            float o0 = c[mi][ni][0] + bb.x, o1 = c[mi][ni][1] + bb.y;
            float o2 = c[mi][ni][2] + bb.x, o3 = c[mi][ni][3] + bb.y;
            if (ROUND_OUT) {
                o0 = __uint_as_float(f2tf32(o0)); o1 = __uint_as_float(f2tf32(o1));
                o2 = __uint_as_float(f2tf32(o2)); o3 = __uint_as_float(f2tf32(o3));
            }
            *(float2*)(C + (size_t)r * N + cc)       = make_float2(o0, o1);
            *(float2*)(C + (size_t)(r + 8) * N + cc) = make_float2(o2, o3);
        }
    }
}

// ---------------------------------------------------------------------------
// tf32 flash attention (causal). hidden is PRE-ROUNDED tf32 -> no cvt on
// Q/K/V paths; 1/sqrt(d) folded in after the S MMAs. Q block 128, key tile 64.
// ---------------------------------------------------------------------------
#define QS_S 132
#define KS_S 132
#define VS_S 136
#define PS_S 68
#define AT_SMEM ((128*QS_S + 64*KS_S + 64*VS_S + 128*PS_S)*4)

__global__ __launch_bounds__(256, 1) void flash_tf32(
    const float* __restrict__ hidden, float* __restrict__ z)
{
    extern __shared__ uint32_t sm[];
    uint32_t* Qs = sm;                   // [128][QS_S]
    uint32_t* Ks = Qs + 128*QS_S;        // [64][KS_S]
    uint32_t* Vs = Ks + 64*KS_S;         // [64][VS_S]
    uint32_t* Ps = Vs + 64*VS_S;         // [128][PS_S]

    const int h    = blockIdx.y;
    const int qb   = (int)(gridDim.x - 1) - (int)blockIdx.x;
    const int tid  = threadIdx.x;
    const int lane = tid & 31;
    const int warp = tid >> 5;
    const int m0   = warp * 16;
    const int ra   = lane >> 2;
    const int kq   = lane & 3;
    const float scale = 0.08838834764831845f;  // 1/sqrt(128)

    uint32_t asK = (uint32_t)__cvta_generic_to_shared(Ks);
    uint32_t asV = (uint32_t)__cvta_generic_to_shared(Vs);

    // Q tile: straight copy (already tf32-rounded)
    #pragma unroll
    for (int i = 0; i < 16; i++) {
        int idx = tid + 256*i;
        int r = idx >> 5, d4 = (idx & 31) << 2;
        *(uint4*)&Qs[r*QS_S + d4] =
            *(const uint4*)(hidden + (size_t)(qb*128 + r)*QKV_N + h*HD + d4);
    }

    float m_a = -1e30f, m_b = -1e30f, l_a = 0.f, l_b = 0.f;
    float o[16][4];
    #pragma unroll
    for (int ni = 0; ni < 16; ni++)
        o[ni][0] = o[ni][1] = o[ni][2] = o[ni][3] = 0.f;

    const int qr_a = qb*128 + m0 + ra;
    const int nkb  = 2*qb + 2;

    for (int kb = 0; kb < nkb; kb++) {
        __syncthreads();
        // K/V tiles via cp.async (no cvt needed)
        #pragma unroll
        for (int i = 0; i < 8; i++) {
            int idx = tid + 256*i;
            int r = idx >> 5, d4 = (idx & 31) << 2;
            const float* kp = hidden + (size_t)(kb*64 + r)*QKV_N + MODEL + h*HD + d4;
            cp16(asK + (uint32_t)(r*KS_S + d4)*4u, kp);
            cp16(asV + (uint32_t)(r*VS_S + d4)*4u, kp + MODEL);
        }
        cp_commit();
        cp_wait<0>();
        __syncthreads();

        // ---- S = Q @ K^T ----
        float s[8][4];
        #pragma unroll
        for (int n = 0; n < 8; n++) s[n][0] = s[n][1] = s[n][2] = s[n][3] = 0.f;

        #pragma unroll
        for (int k0 = 0; k0 < 128; k0 += 8) {
            uint32_t a[4];
            const uint32_t* qp = Qs + (m0 + ra)*QS_S + k0 + kq;
            a[0] = qp[0]; a[1] = qp[8*QS_S]; a[2] = qp[4]; a[3] = qp[8*QS_S + 4];
            #pragma unroll
            for (int n = 0; n < 8; n++) {
                const uint32_t* kp2 = Ks + (n*8 + ra)*KS_S + k0 + kq;
                mma_tf32(s[n], a, kp2[0], kp2[4]);
            }
        }

        // fold 1/sqrt(d)
        #pragma unroll
        for (int n = 0; n < 8; n++) {
            s[n][0] *= scale; s[n][1] *= scale;
            s[n][2] *= scale; s[n][3] *= scale;
        }

        // ---- causal mask (near-diagonal tiles only) ----
        if (kb >= 2*qb) {
            #pragma unroll
            for (int n = 0; n < 8; n++) {
                int col = kb*64 + n*8 + 2*kq;
                if (col     > qr_a)     s[n][0] = -1e30f;
                if (col + 1 > qr_a)     s[n][1] = -1e30f;
                if (col     > qr_a + 8) s[n][2] = -1e30f;
                if (col + 1 > qr_a + 8) s[n][3] = -1e30f;
            }
        }

        // ---- online softmax ----
        float mxa = -1e30f, mxb = -1e30f;
        #pragma unroll
        for (int n = 0; n < 8; n++) {
            mxa = fmaxf(mxa, fmaxf(s[n][0], s[n][1]));
            mxb = fmaxf(mxb, fmaxf(s[n][2], s[n][3]));
        }
        mxa = fmaxf(mxa, __shfl_xor_sync(0xffffffffu, mxa, 1));
        mxa = fmaxf(mxa, __shfl_xor_sync(0xffffffffu, mxa, 2));
        mxb = fmaxf(mxb, __shfl_xor_sync(0xffffffffu, mxb, 1));
        mxb = fmaxf(mxb, __shfl_xor_sync(0xffffffffu, mxb, 2));

        float mna = fmaxf(m_a, mxa), mnb = fmaxf(m_b, mxb);
        float alpha_a = __expf(m_a - mna), alpha_b = __expf(m_b - mnb);
        float suma = 0.f, sumb = 0.f;
        #pragma unroll
        for (int n = 0; n < 8; n++) {
            float p0 = __expf(s[n][0] - mna), p1 = __expf(s[n][1] - mna);
            float p2 = __expf(s[n][2] - mnb), p3 = __expf(s[n][3] - mnb);
            suma += p0 + p1; sumb += p2 + p3;
            uint32_t* pp = Ps + (m0 + ra)*PS_S + n*8 + 2*kq;
            pp[0] = f2tf32(p0); pp[1] = f2tf32(p1);
            pp[8*PS_S] = f2tf32(p2); pp[8*PS_S + 1] = f2tf32(p3);
        }
        suma += __shfl_xor_sync(0xffffffffu, suma, 1);
        suma += __shfl_xor_sync(0xffffffffu, suma, 2);
        sumb += __shfl_xor_sync(0xffffffffu, sumb, 1);
        sumb += __shfl_xor_sync(0xffffffffu, sumb, 2);
        l_a = l_a * alpha_a + suma;
        l_b = l_b * alpha_b + sumb;
        m_a = mna; m_b = mnb;
        #pragma unroll
        for (int ni = 0; ni < 16; ni++) {
            o[ni][0] *= alpha_a; o[ni][1] *= alpha_a;
            o[ni][2] *= alpha_b; o[ni][3] *= alpha_b;
        }
        __syncwarp();

        // ---- O += P @ V ----
        #pragma unroll
        for (int k0 = 0; k0 < 64; k0 += 8) {
            uint32_t a[4];
            const uint32_t* pp = Ps + (m0 + ra)*PS_S + k0 + kq;
            a[0] = pp[0]; a[1] = pp[8*PS_S]; a[2] = pp[4]; a[3] = pp[8*PS_S + 4];
            #pragma unroll
            for (int ni = 0; ni < 16; ni++) {
                const uint32_t* vp = Vs + (k0 + kq)*VS_S + ni*8 + ra;
                mma_tf32(o[ni], a, vp[0], vp[4*VS_S]);
            }
        }
        __syncwarp();
    }

    // ---- normalize + write z rounded (proj GEMM reads cvt-free) ----
    float inva = 1.f / l_a, invb = 1.f / l_b;
    #pragma unroll
    for (int ni = 0; ni < 16; ni++) {
        int cc = h*HD + ni*8 + 2*kq;
        int r  = qb*128 + m0 + ra;
        uint2 v0 = make_uint2(f2tf32(o[ni][0]*inva), f2tf32(o[ni][1]*inva));
        uint2 v1 = make_uint2(f2tf32(o[ni][2]*invb), f2tf32(o[ni][3]*invb));
        *(uint2*)(z + (size_t)r * MODEL + cc)       = v0;
        *(uint2*)(z + (size_t)(r + 8) * MODEL + cc) = v1;
    }
}

// ---------------------------------------------------------------------------
extern "C" void kernel_launch(void* const* d_in, const int* in_sizes, int n_in,
                              void* d_out, int out_size)
{
    const float* x      = (const float*)d_in[0];
    const float* w_attn = (const float*)d_in[1];
    const float* b_attn = (const float*)d_in[2];
    const float* w_proj = (const float*)d_in[3];
    const float* b_proj = (const float*)d_in[4];
    float* out = (float*)d_out;

    float *hid, *z, *xr, *wa, *wp;
    cudaGetSymbolAddress((void**)&hid, g_hidden);
    cudaGetSymbolAddress((void**)&z,   g_z);
    cudaGetSymbolAddress((void**)&xr,  g_xr);
    cudaGetSymbolAddress((void**)&wa,  g_wa);
    cudaGetSymbolAddress((void**)&wp,  g_wp);

    cudaFuncSetAttribute(gemm_tf32<true>,
                         cudaFuncAttributeMaxDynamicSharedMemorySize, GEMM_SMEM);
    cudaFuncSetAttribute(gemm_tf32<false>,
                         cudaFuncAttributeMaxDynamicSharedMemorySize, GEMM_SMEM);
    cudaFuncSetAttribute(flash_tf32,
                         cudaFuncAttributeMaxDynamicSharedMemorySize, AT_SMEM);

    // 0) pre-round GEMM operands (numerics-identical to per-load cvt)
    round_tf32_kernel<<<2048, 256>>>(x,      xr, SEQ*MODEL);
    round_tf32_kernel<<<2048, 256>>>(w_attn, wa, MODEL*QKV_N);
    round_tf32_kernel<<<2048, 256>>>(w_proj, wp, MODEL*MODEL);

    // 1) QKV projection (rounded output feeds flash cvt-free)
    gemm_tf32<true><<<dim3(QKV_N/128, SEQ/128), 256, GEMM_SMEM>>>(
        xr, wa, b_attn, hid, SEQ, QKV_N, MODEL);

    // 2) causal multi-head attention (writes rounded z)
    flash_tf32<<<dim3(SEQ/128, NH), 256, AT_SMEM>>>(hid, z);

    // 3) output projection (fp32 output)
    gemm_tf32<false><<<dim3(MODEL/128, SEQ/128), 256, GEMM_SMEM>>>(
        z, wp, b_proj, out, SEQ, MODEL, MODEL);
}

// round 7
// speedup vs baseline: 5.1015x; 1.0339x over previous
#include <cuda_runtime.h>
#include <math.h>
#include <stdint.h>

#define SEQ   4096
#define MODEL 2048
#define NH    16
#define HD    128
#define QKV_N (3*MODEL)

// Scratch (__device__ globals: allocation-free rule)
__device__ float g_hidden[(size_t)SEQ * QKV_N];
__device__ float g_z[(size_t)SEQ * MODEL];
__device__ float g_xr[(size_t)SEQ * MODEL];     // rounded x      [SEQ][MODEL]
__device__ float g_wa[(size_t)MODEL * QKV_N];   // rounded w_attn [MODEL][QKV_N]
__device__ float g_wp[(size_t)MODEL * MODEL];   // rounded w_proj [MODEL][MODEL]

__device__ __forceinline__ uint32_t f2tf32(float f) {
    uint32_t u; asm("cvt.rna.tf32.f32 %0, %1;" : "=r"(u) : "f"(f)); return u;
}
__device__ __forceinline__ void mma_tf32(float* c, const uint32_t* a,
                                         uint32_t b0, uint32_t b1) {
    asm volatile(
        "mma.sync.aligned.m16n8k8.row.col.f32.tf32.tf32.f32 "
        "{%0,%1,%2,%3}, {%4,%5,%6,%7}, {%8,%9}, {%0,%1,%2,%3};\n"
        : "+f"(c[0]), "+f"(c[1]), "+f"(c[2]), "+f"(c[3])
        : "r"(a[0]), "r"(a[1]), "r"(a[2]), "r"(a[3]), "r"(b0), "r"(b1));
}
__device__ __forceinline__ void cp16(uint32_t dst, const void* src) {
    asm volatile("cp.async.cg.shared.global [%0], [%1], 16;\n" :: "r"(dst), "l"(src));
}
__device__ __forceinline__ void cp_commit() { asm volatile("cp.async.commit_group;\n"); }
template<int N> __device__ __forceinline__ void cp_wait() {
    asm volatile("cp.async.wait_group %0;\n" :: "n"(N));
}
__device__ __forceinline__ uint32_t smem_u32(const void* p) {
    uint32_t a;
    asm("{ .reg .u64 t; cvta.to.shared.u64 t, %1; cvt.u32.u64 %0, t; }"
        : "=r"(a) : "l"(p));
    return a;
}

// ---------------------------------------------------------------------------
// Pre-round fp32 -> tf32 (RNA)
// ---------------------------------------------------------------------------
__global__ void round_tf32_kernel(const float* __restrict__ in,
                                  float* __restrict__ out, int n) {
    int i = (blockIdx.x * blockDim.x + threadIdx.x) * 4;
    int stride = gridDim.x * blockDim.x * 4;
    for (; i < n; i += stride) {
        float4 v = *(const float4*)(in + i);
        *(uint4*)(out + i) = make_uint4(f2tf32(v.x), f2tf32(v.y),
                                        f2tf32(v.z), f2tf32(v.w));
    }
}

// ---------------------------------------------------------------------------
// tf32 GEMM: C[M,N] = A[M,K]@B[K,N] + bias. A,B pre-rounded tf32 bits.
// Block 256x128, BK=16, 256 thr = 8 warps (4x2), warp tile 64x64 (128 accums),
// cp.async 4-stage. LDS:MMA = 1:1 per k8 step.
// ---------------------------------------------------------------------------
#define GS 4
#define ASTRIDE 20
#define BSTRIDE 136
#define A_TILE (256*ASTRIDE)
#define B_TILE (16*BSTRIDE)
#define GEMM_SMEM ((GS*(A_TILE+B_TILE))*4)

template<bool ROUND_OUT>
__global__ __launch_bounds__(256, 1) void gemm_tf32(
    const float* __restrict__ A, const float* __restrict__ B,
    const float* __restrict__ bias, float* __restrict__ C,
    int M, int N, int K)
{
    extern __shared__ uint32_t gsm[];
    uint32_t* As = gsm;                  // [GS][256][ASTRIDE]  ([m][k])
    uint32_t* Bs = gsm + GS*A_TILE;      // [GS][16][BSTRIDE]   ([k][n])

    const int tid  = threadIdx.x;
    const int lane = tid & 31;
    const int warp = tid >> 5;
    const int ra   = lane >> 2;
    const int kq   = lane & 3;
    const int m0 = (warp >> 1) * 64;
    const int n0 = (warp & 1) * 64;
    const int row0 = blockIdx.y * 256, col0 = blockIdx.x * 128;

    const int art = tid >> 2, acol = (tid & 3) * 4;   // A: 4 rows x 16B
    const int bkr = tid >> 4, bcol = (tid & 15) * 8;  // B: 1 row  x 2x16B

    uint32_t asA = (uint32_t)__cvta_generic_to_shared(As);
    uint32_t asB = (uint32_t)__cvta_generic_to_shared(Bs);
    const int niter = K >> 4;

    auto issue = [&](int t) {
        int st = t & (GS - 1);
        const float* ap = A + (size_t)(row0 + art) * K + t*16 + acol;
        uint32_t ad = asA + (uint32_t)(st*A_TILE + art*ASTRIDE + acol) * 4u;
        cp16(ad, ap);
        cp16(ad +  64u*ASTRIDE*4u, ap + (size_t) 64 * K);
        cp16(ad + 128u*ASTRIDE*4u, ap + (size_t)128 * K);
        cp16(ad + 192u*ASTRIDE*4u, ap + (size_t)192 * K);
        const float* bp = B + (size_t)(t*16 + bkr) * N + col0 + bcol;
        uint32_t bd = asB + (uint32_t)(st*B_TILE + bkr*BSTRIDE + bcol) * 4u;
        cp16(bd, bp);
        cp16(bd + 16u, bp + 4);
    };

    #pragma unroll
    for (int s = 0; s < GS - 1; s++) { issue(s); cp_commit(); }

    float c[4][8][4];
    #pragma unroll
    for (int mi = 0; mi < 4; mi++)
        #pragma unroll
        for (int ni = 0; ni < 8; ni++)
            #pragma unroll
            for (int r = 0; r < 4; r++) c[mi][ni][r] = 0.f;

    for (int i = 0; i < niter; i++) {
        cp_wait<GS-2>();
        __syncthreads();
        if (i + GS - 1 < niter) issue(i + GS - 1);
        cp_commit();

        const uint32_t* Ab = As + (size_t)(i & (GS-1)) * A_TILE;
        const uint32_t* Bb = Bs + (size_t)(i & (GS-1)) * B_TILE;

        #pragma unroll
        for (int kk = 0; kk < 16; kk += 8) {
            uint32_t af[4][4];
            #pragma unroll
            for (int mi = 0; mi < 4; mi++) {
                const uint32_t* p = Ab + (m0 + mi*16 + ra)*ASTRIDE + kk + kq;
                af[mi][0] = p[0];
                af[mi][1] = p[8*ASTRIDE];
                af[mi][2] = p[4];
                af[mi][3] = p[8*ASTRIDE + 4];
            }
            uint32_t bf[8][2];
            #pragma unroll
            for (int ni = 0; ni < 8; ni++) {
                const uint32_t* bp = Bb + (kk + kq)*BSTRIDE + n0 + ni*8 + ra;
                bf[ni][0] = bp[0];
                bf[ni][1] = bp[4*BSTRIDE];
            }
            #pragma unroll
            for (int ni = 0; ni < 8; ni++)
                #pragma unroll
                for (int mi = 0; mi < 4; mi++)
                    mma_tf32(c[mi][ni], af[mi], bf[ni][0], bf[ni][1]);
        }
    }

    #pragma unroll
    for (int ni = 0; ni < 8; ni++) {
        int cc = col0 + n0 + ni*8 + 2*kq;
        float2 bb = *(const float2*)(bias + cc);
        #pragma unroll
        for (int mi = 0; mi < 4; mi++) {
            int r = row0 + m0 + mi*16 + ra;
            float o0 = c[mi][ni][0] + bb.x, o1 = c[mi][ni][1] + bb.y;
            float o2 = c[mi][ni][2] + bb.x, o3 = c[mi][ni][3] + bb.y;
            if (ROUND_OUT) {
                o0 = __uint_as_float(f2tf32(o0)); o1 = __uint_as_float(f2tf32(o1));
                o2 = __uint_as_float(f2tf32(o2)); o3 = __uint_as_float(f2tf32(o3));
            }
            *(float2*)(C + (size_t)r * N + cc)       = make_float2(o0, o1);
            *(float2*)(C + (size_t)(r + 8) * N + cc) = make_float2(o2, o3);
        }
    }
}

// ---------------------------------------------------------------------------
// tf32 flash attention (causal). Q block 128 (fragments in REGISTERS),
// key tile 64, K/V double-buffered cp.async pipeline (prefetch kb+2 while
// computing kb). 8 warps x 16 q-rows. hidden pre-rounded tf32.
// ---------------------------------------------------------------------------
#define KS_S 132
#define VS_S 136
#define PS_S 68
#define FL_SMEM ((2*64*KS_S + 2*64*VS_S + 128*PS_S)*4)

__global__ __launch_bounds__(256, 1) void flash_tf32(
    const float* __restrict__ hidden, float* __restrict__ z)
{
    extern __shared__ uint32_t sm[];
    uint32_t* Ks = sm;                    // [2][64][KS_S]
    uint32_t* Vs = Ks + 2*64*KS_S;        // [2][64][VS_S]
    uint32_t* Ps = Vs + 2*64*VS_S;        // [128][PS_S]

    const int h    = blockIdx.y;
    const int qb   = (int)(gridDim.x - 1) - (int)blockIdx.x;  // heavy first
    const int tid  = threadIdx.x;
    const int lane = tid & 31;
    const int warp = tid >> 5;
    const int m0   = warp * 16;
    const int ra   = lane >> 2;
    const int kq   = lane & 3;
    const float scale = 0.08838834764831845f;  // 1/sqrt(128)

    uint32_t asK = smem_u32(Ks);
    uint32_t asV = smem_u32(Vs);

    auto load_tile = [&](int t) {
        uint32_t kb_ = asK + (uint32_t)(t & 1) * 64u*KS_S*4u;
        uint32_t vb_ = asV + (uint32_t)(t & 1) * 64u*VS_S*4u;
        #pragma unroll
        for (int i = 0; i < 8; i++) {
            int idx = tid + 256*i;
            int r = idx >> 5, d4 = (idx & 31) << 2;
            const float* kp = hidden + (size_t)(t*64 + r)*QKV_N + MODEL + h*HD + d4;
            cp16(kb_ + (uint32_t)(r*KS_S + d4)*4u, kp);
            cp16(vb_ + (uint32_t)(r*VS_S + d4)*4u, kp + MODEL);
        }
        cp_commit();
    };

    // Q fragments straight to registers (values already tf32-rounded)
    uint32_t qf[16][4];
    {
        const float* qp0 = hidden + (size_t)(qb*128 + m0 + ra)*QKV_N + h*HD;
        const float* qp1 = qp0 + (size_t)8*QKV_N;
        #pragma unroll
        for (int i = 0; i < 16; i++) {
            qf[i][0] = __float_as_uint(qp0[i*8 + kq]);
            qf[i][1] = __float_as_uint(qp1[i*8 + kq]);
            qf[i][2] = __float_as_uint(qp0[i*8 + kq + 4]);
            qf[i][3] = __float_as_uint(qp1[i*8 + kq + 4]);
        }
    }

    float m_a = -1e30f, m_b = -1e30f, l_a = 0.f, l_b = 0.f;
    float o[16][4];
    #pragma unroll
    for (int ni = 0; ni < 16; ni++)
        o[ni][0] = o[ni][1] = o[ni][2] = o[ni][3] = 0.f;

    const int qr_a = qb*128 + m0 + ra;
    const int nkb  = 2*qb + 2;

    load_tile(0);
    load_tile(1);

    for (int kb = 0; kb < nkb; kb++) {
        cp_wait<1>();          // tile kb resident (kb+1 may still be in flight)
        __syncthreads();

        const uint32_t* Kb = Ks + (kb & 1)*64*KS_S;
        const uint32_t* Vb = Vs + (kb & 1)*64*VS_S;

        // ---- S = Q @ K^T (Q from registers) ----
        float s[8][4];
        #pragma unroll
        for (int n = 0; n < 8; n++) s[n][0] = s[n][1] = s[n][2] = s[n][3] = 0.f;

        #pragma unroll
        for (int i = 0; i < 16; i++) {
            #pragma unroll
            for (int n = 0; n < 8; n++) {
                const uint32_t* kp2 = Kb + (n*8 + ra)*KS_S + i*8 + kq;
                mma_tf32(s[n], qf[i], kp2[0], kp2[4]);
            }
        }

        #pragma unroll
        for (int n = 0; n < 8; n++) {
            s[n][0] *= scale; s[n][1] *= scale;
            s[n][2] *= scale; s[n][3] *= scale;
        }

        // ---- causal mask (near-diagonal tiles only) ----
        if (kb >= 2*qb) {
            #pragma unroll
            for (int n = 0; n < 8; n++) {
                int col = kb*64 + n*8 + 2*kq;
                if (col     > qr_a)     s[n][0] = -1e30f;
                if (col + 1 > qr_a)     s[n][1] = -1e30f;
                if (col     > qr_a + 8) s[n][2] = -1e30f;
                if (col + 1 > qr_a + 8) s[n][3] = -1e30f;
            }
        }

        // ---- online softmax ----
        float mxa = -1e30f, mxb = -1e30f;
        #pragma unroll
        for (int n = 0; n < 8; n++) {
            mxa = fmaxf(mxa, fmaxf(s[n][0], s[n][1]));
            mxb = fmaxf(mxb, fmaxf(s[n][2], s[n][3]));
        }
        mxa = fmaxf(mxa, __shfl_xor_sync(0xffffffffu, mxa, 1));
        mxa = fmaxf(mxa, __shfl_xor_sync(0xffffffffu, mxa, 2));
        mxb = fmaxf(mxb, __shfl_xor_sync(0xffffffffu, mxb, 1));
        mxb = fmaxf(mxb, __shfl_xor_sync(0xffffffffu, mxb, 2));

        float mna = fmaxf(m_a, mxa), mnb = fmaxf(m_b, mxb);
        float alpha_a = __expf(m_a - mna), alpha_b = __expf(m_b - mnb);
        float suma = 0.f, sumb = 0.f;
        #pragma unroll
        for (int n = 0; n < 8; n++) {
            float p0 = __expf(s[n][0] - mna), p1 = __expf(s[n][1] - mna);
            float p2 = __expf(s[n][2] - mnb), p3 = __expf(s[n][3] - mnb);
            suma += p0 + p1; sumb += p2 + p3;
            uint32_t* pp = Ps + (m0 + ra)*PS_S + n*8 + 2*kq;
            pp[0] = f2tf32(p0); pp[1] = f2tf32(p1);
            pp[8*PS_S] = f2tf32(p2); pp[8*PS_S + 1] = f2tf32(p3);
        }
        suma += __shfl_xor_sync(0xffffffffu, suma, 1);
        suma += __shfl_xor_sync(0xffffffffu, suma, 2);
        sumb += __shfl_xor_sync(0xffffffffu, sumb, 1);
        sumb += __shfl_xor_sync(0xffffffffu, sumb, 2);
        l_a = l_a * alpha_a + suma;
        l_b = l_b * alpha_b + sumb;
        m_a = mna; m_b = mnb;
        #pragma unroll
        for (int ni = 0; ni < 16; ni++) {
            o[ni][0] *= alpha_a; o[ni][1] *= alpha_a;
            o[ni][2] *= alpha_b; o[ni][3] *= alpha_b;
        }
        __syncwarp();

        // ---- O += P @ V ----
        #pragma unroll
        for (int k0 = 0; k0 < 64; k0 += 8) {
            uint32_t a[4];
            const uint32_t* pp = Ps + (m0 + ra)*PS_S + k0 + kq;
            a[0] = pp[0]; a[1] = pp[8*PS_S]; a[2] = pp[4]; a[3] = pp[8*PS_S + 4];
            #pragma unroll
            for (int ni = 0; ni < 16; ni++) {
                const uint32_t* vp = Vb + (k0 + kq)*VS_S + ni*8 + ra;
                mma_tf32(o[ni], a, vp[0], vp[4*VS_S]);
            }
        }

        __syncthreads();           // all warps done with buf[kb&1]
        if (kb + 2 < nkb) load_tile(kb + 2);
        else              cp_commit();   // dummy group keeps wait<1> semantics
    }

    // ---- normalize + write z rounded (proj GEMM reads cvt-free) ----
    float inva = 1.f / l_a, invb = 1.f / l_b;
    #pragma unroll
    for (int ni = 0; ni < 16; ni++) {
        int cc = h*HD + ni*8 + 2*kq;
        int r  = qb*128 + m0 + ra;
        uint2 v0 = make_uint2(f2tf32(o[ni][0]*inva), f2tf32(o[ni][1]*inva));
        uint2 v1 = make_uint2(f2tf32(o[ni][2]*invb), f2tf32(o[ni][3]*invb));
        *(uint2*)(z + (size_t)r * MODEL + cc)       = v0;
        *(uint2*)(z + (size_t)(r + 8) * MODEL + cc) = v1;
    }
}

// ---------------------------------------------------------------------------
extern "C" void kernel_launch(void* const* d_in, const int* in_sizes, int n_in,
                              void* d_out, int out_size)
{
    const float* x      = (const float*)d_in[0];
    const float* w_attn = (const float*)d_in[1];
    const float* b_attn = (const float*)d_in[2];
    const float* w_proj = (const float*)d_in[3];
    const float* b_proj = (const float*)d_in[4];
    float* out = (float*)d_out;

    float *hid, *z, *xr, *wa, *wp;
    cudaGetSymbolAddress((void**)&hid, g_hidden);
    cudaGetSymbolAddress((void**)&z,   g_z);
    cudaGetSymbolAddress((void**)&xr,  g_xr);
    cudaGetSymbolAddress((void**)&wa,  g_wa);
    cudaGetSymbolAddress((void**)&wp,  g_wp);

    cudaFuncSetAttribute(gemm_tf32<true>,
                         cudaFuncAttributeMaxDynamicSharedMemorySize, GEMM_SMEM);
    cudaFuncSetAttribute(gemm_tf32<false>,
                         cudaFuncAttributeMaxDynamicSharedMemorySize, GEMM_SMEM);
    cudaFuncSetAttribute(flash_tf32,
                         cudaFuncAttributeMaxDynamicSharedMemorySize, FL_SMEM);

    // 0) pre-round GEMM operands (numerics-identical to per-load cvt)
    round_tf32_kernel<<<2048, 256>>>(x,      xr, SEQ*MODEL);
    round_tf32_kernel<<<2048, 256>>>(w_attn, wa, MODEL*QKV_N);
    round_tf32_kernel<<<2048, 256>>>(w_proj, wp, MODEL*MODEL);

    // 1) QKV projection (rounded output feeds flash cvt-free)
    gemm_tf32<true><<<dim3(QKV_N/128, SEQ/256), 256, GEMM_SMEM>>>(
        xr, wa, b_attn, hid, SEQ, QKV_N, MODEL);

    // 2) causal multi-head attention (writes rounded z)
    flash_tf32<<<dim3(SEQ/128, NH), 256, FL_SMEM>>>(hid, z);

    // 3) output projection (fp32 output)
    gemm_tf32<false><<<dim3(MODEL/128, SEQ/256), 256, GEMM_SMEM>>>(
        z, wp, b_proj, out, SEQ, MODEL, MODEL);
}